// round 16
// baseline (speedup 1.0000x reference)
#include <cuda_runtime.h>
#include <cuda_fp16.h>

#define NN 20000
#define NE 320000
#define NB 25
#define SEG 800
#define FULLMASK 0xffffffffu
#define CSTF 1e-5f
#define CSRB 148
#define NTILES 313          // 313*64 = 20032 >= 20000
#define NWORK (3*NTILES)    // 939 GEMM tiles
#define GRIDF 740           // 148 CSR + 592 workers; one wave at 5 blocks/SM

#define FMA2(acc, a, b) asm("fma.rn.f32x2 %0, %1, %2, %0;" : "+l"(acc) : "l"(a), "l"(b))
#define PACK2(xx, xv)   asm("mov.b64 %0, {%1, %1};" : "=l"(xx) : "f"(xv))

union U2 { unsigned long long u; float2 f; };

// ---------------- device scratch (static; every call restores zeros) ----------------
__device__ float  g_Q[NN*64];
__device__ __half g_Kh[NN*64];
__device__ __half g_Vh[NN*64];
__device__ float  g_V[NN*64];
__device__ float  g_hidden[NN*64];
__device__ __half g_M1h[(size_t)NN*512];
__device__ __half g_K1h[NN*64];
__device__ float  g_deginv[NN];
__device__ int    g_cnt[NN];
__device__ int    g_cur[NN];
__device__ int    g_colptr[NN+1];
__device__ int    g_bsum[NB];
__device__ int    g_boff[NB+1];
__device__ int    g_srow[NE];
__device__ float  g_snorm[NE];
__device__ volatile int g_ph1, g_ph2, g_ph3;
__device__ int    g_work;           // GEMM tile queue; reset in k_pass1 for next replay

__device__ __forceinline__ void detect64(const int* __restrict__ ei, int tid, int* s64){
  if(tid < 32){
    bool z = (ei[2*(tid*9973)+1] == 0);
    unsigned bal = __ballot_sync(FULLMASK, z);
    if(tid==0) *s64 = (bal == FULLMASK) ? 1 : 0;
  }
}

__device__ __forceinline__ int colp(int i){
  return g_colptr[i] + g_boff[i/SEG];
}

// ---------------- GEMM tile worker (work-stealing) ----------------
__device__ void gemm_worker(char* dsm, int tid,
    const float* __restrict__ x,
    const float* __restrict__ Wq, const float* __restrict__ bq,
    const float* __restrict__ Wk, const float* __restrict__ bk,
    const float* __restrict__ Wv, const float* __restrict__ bv){
  float*  xst = (float*)dsm;
  float2* ws2 = (float2*)(dsm + 16896);
  float2* bs2 = (float2*)(dsm + 16896 + 16384);
  int* tslot  = (int*)  (dsm + 16896 + 16384 + 256);
  int curmat = -1;
  int op = tid & 31;
  int ng = (tid >> 5) << 3;
  const unsigned long long* wsu = (const unsigned long long*)ws2;

  while(true){
    __syncthreads();
    if(tid == 0) *tslot = atomicAdd(&g_work, 1);
    __syncthreads();
    int t = *tslot;
    if(t >= NWORK) break;
    int mat  = t / NTILES;
    int tile = t - mat*NTILES;
    int nb   = tile*64;
    const float* W = (mat==0) ? Wq : (mat==1) ? Wk : Wv;
    const float* b = (mat==0) ? bq : (mat==1) ? bk : bv;

    for(int idx = tid; idx < 4096; idx += 256){
      int n = idx >> 6, i = idx & 63;
      xst[i*66 + n] = (nb+n < NN) ? x[(nb+n)*64 + i] : 0.f;
    }
    if(mat != curmat){
      for(int idx = tid; idx < 4096; idx += 256){
        int wi = idx >> 6, wo = idx & 63;
        ((float*)&ws2[wi*32 + (wo & 31)])[wo >> 5] = W[idx];
      }
      if(tid < 32) bs2[tid] = make_float2(b[tid], b[tid+32]);
      curmat = mat;
    }
    __syncthreads();

    U2 a0[4], a1[4];
    { float2 bb = bs2[op];
      unsigned long long p0, p1; PACK2(p0, bb.x); PACK2(p1, bb.y);
      #pragma unroll
      for(int g=0;g<4;g++){ a0[g].u = p0; a1[g].u = p1; } }

    #pragma unroll 4
    for(int i=0; i<64; i++){
      U2 w; w.u = wsu[i*32 + op];
      unsigned long long w0, w1; PACK2(w0, w.f.x); PACK2(w1, w.f.y);
      const unsigned long long* xp = (const unsigned long long*)&xst[i*66 + ng];
      #pragma unroll
      for(int g=0;g<4;g++){
        unsigned long long xx = xp[g];
        FMA2(a0[g].u, xx, w0);
        FMA2(a1[g].u, xx, w1);
      }
    }

    #pragma unroll
    for(int g=0;g<4;g++){
      int n0 = nb + ng + 2*g;
      #pragma unroll
      for(int u=0;u<2;u++){
        int n = n0 + u;
        if(n < NN){
          float va = u ? a0[g].f.y : a0[g].f.x;
          float vb = u ? a1[g].f.y : a1[g].f.x;
          if(mat == 0){
            va = (va > 0.f) ? (va + 1.f) : __expf(va);
            vb = (vb > 0.f) ? (vb + 1.f) : __expf(vb);
            g_Q[n*64+op] = va; g_Q[n*64+op+32] = vb;
          } else if(mat == 1){
            va = (va > 0.f) ? (va + 1.f) : __expf(va);
            vb = (vb > 0.f) ? (vb + 1.f) : __expf(vb);
            g_Kh[n*64+op] = __float2half_rn(va); g_Kh[n*64+op+32] = __float2half_rn(vb);
          } else {
            g_V[n*64+op] = va; g_V[n*64+op+32] = vb;
            g_Vh[n*64+op] = __float2half_rn(va); g_Vh[n*64+op+32] = __float2half_rn(vb);
          }
        }
      }
    }
  }
}

// ============ fused launch: 148 CSR blocks (then join queue) + 592 workers ============
#define SMEMF (16896 + 16384 + 256 + 16)
__global__ void __launch_bounds__(256,5) k_fused(const int* __restrict__ ei,
    const float* __restrict__ x,
    const float* __restrict__ Wq, const float* __restrict__ bq,
    const float* __restrict__ Wk, const float* __restrict__ bk,
    const float* __restrict__ Wv, const float* __restrict__ bv){
  extern __shared__ __align__(16) char dsm[];
  int tid = threadIdx.x;
  int bid = blockIdx.x;

  if(bid < CSRB){
    int* s     = (int*)dsm;
    int* wtot  = (int*)(dsm + SEG*4);
    int* ps64  = (int*)(dsm + SEG*4 + 32);
    int* sboff = (int*)(dsm + SEG*4 + 64);
    detect64(ei, tid, ps64);
    __syncthreads();
    int s64 = *ps64;

    // phase 1: degree histogram
    for(int e = bid*256 + tid; e < NE; e += CSRB*256){
      int c = s64 ? ei[2*(NE+e)] : ei[NE+e];
      atomicAdd(&g_cnt[c], 1);
    }
    __threadfence();
    __syncthreads();
    if(tid == 0){
      atomicAdd((int*)&g_ph1, 1);
      while(g_ph1 < CSRB) {}
    }
    __syncthreads();
    __threadfence();

    // phase 2: per-segment scan + deginv; zero g_cnt
    if(bid < NB){
      for(int i=tid; i<SEG; i+=256){ s[i] = __ldcg(&g_cnt[bid*SEG+i]); g_cnt[bid*SEG+i] = 0; }
      __syncthreads();
      int c0=0,c1=0,c2=0,c3=0,v=0;
      if(tid < 200){
        c0=s[4*tid]; c1=s[4*tid+1]; c2=s[4*tid+2]; c3=s[4*tid+3];
        v = c0+c1+c2+c3;
      }
      int lane = tid & 31, wid = tid >> 5;
      int xx = v;
      #pragma unroll
      for(int off=1; off<32; off<<=1){ int y=__shfl_up_sync(FULLMASK,xx,off); if(lane>=off) xx+=y; }
      if(lane==31) wtot[wid] = xx;
      __syncthreads();
      if(tid < 32){
        int w = (tid < 7) ? wtot[tid] : 0;
        #pragma unroll
        for(int off=1; off<32; off<<=1){ int y=__shfl_up_sync(FULLMASK,w,off); if(tid>=off) w+=y; }
        if(tid < 7) wtot[tid] = w;
        if(tid == 6) g_bsum[bid] = w;
      }
      __syncthreads();
      if(tid < 200){
        int pre = xx - v + (wid>0 ? wtot[wid-1] : 0);
        int base = bid*SEG + 4*tid;
        g_colptr[base+0] = pre;
        g_colptr[base+1] = pre + c0;
        g_colptr[base+2] = pre + c0 + c1;
        g_colptr[base+3] = pre + c0 + c1 + c2;
        g_deginv[base+0] = c0 ? rsqrtf((float)c0) : 0.f;
        g_deginv[base+1] = c1 ? rsqrtf((float)c1) : 0.f;
        g_deginv[base+2] = c2 ? rsqrtf((float)c2) : 0.f;
        g_deginv[base+3] = c3 ? rsqrtf((float)c3) : 0.f;
      }
    }
    __threadfence();
    __syncthreads();
    if(tid == 0){
      atomicAdd((int*)&g_ph2, 1);
      while(g_ph2 < CSRB) {}
      if(bid == 0) g_ph1 = 0;
    }
    __syncthreads();
    __threadfence();

    // phase 3: block offsets + scatter
    if(tid < 32){
      int v = (tid < NB) ? __ldcg(&g_bsum[tid]) : 0;
      int xx = v;
      #pragma unroll
      for(int off=1; off<32; off<<=1){ int y=__shfl_up_sync(FULLMASK,xx,off); if(tid>=off) xx+=y; }
      if(tid < NB) sboff[tid] = xx - v;
      if(bid == 0){
        if(tid < NB) g_boff[tid] = xx - v;
        if(tid == 31) g_boff[NB] = NE;
      }
    }
    __syncthreads();
    for(int e = bid*256 + tid; e < NE; e += CSRB*256){
      int r = s64 ? ei[2*e]      : ei[e];
      int c = s64 ? ei[2*(NE+e)] : ei[NE+e];
      int pos = __ldcg(&g_colptr[c]) + sboff[c/SEG] + atomicAdd(&g_cur[c], 1);
      g_srow[pos]  = r;
      g_snorm[pos] = __ldcg(&g_deginv[r]) * __ldcg(&g_deginv[c]);
    }
    __threadfence();
    __syncthreads();
    if(tid == 0){
      atomicAdd((int*)&g_ph3, 1);
      if(bid == 0){
        while(g_ph3 < CSRB) {}
        g_ph2 = 0; g_ph3 = 0;
      }
    }
    __syncthreads();
    gemm_worker(dsm, tid, x, Wq, bq, Wk, bk, Wv, bv);
    return;
  }

  gemm_worker(dsm, tid, x, Wq, bq, Wk, bk, Wv, bv);
}

// ---------------- pass1 edge body ----------------
__device__ __forceinline__ void p1edge(float nrm, __half2 kh, uint4 vv,
                                       float& ka0, float& ka1, U2* m0p, U2* m1p){
  float2 kf = __half22float2(kh);
  float a0 = nrm*kf.x, a1 = nrm*kf.y;
  ka0 += a0; ka1 += a1;
  unsigned long long A0, A1; PACK2(A0, a0); PACK2(A1, a1);
  U2 v01, v23, v45, v67;
  v01.f = __half22float2(*(__half2*)&vv.x);
  v23.f = __half22float2(*(__half2*)&vv.y);
  v45.f = __half22float2(*(__half2*)&vv.z);
  v67.f = __half22float2(*(__half2*)&vv.w);
  FMA2(m0p[0].u, A0, v01.u); FMA2(m0p[1].u, A0, v23.u);
  FMA2(m0p[2].u, A0, v45.u); FMA2(m0p[3].u, A0, v67.u);
  FMA2(m1p[0].u, A1, v01.u); FMA2(m1p[1].u, A1, v23.u);
  FMA2(m1p[2].u, A1, v45.u); FMA2(m1p[3].u, A1, v67.u);
}

// ---------------- hop 1: 2 warps per node (split edge range), unroll-2 ----------------
__global__ void __launch_bounds__(256) k_pass1(const float* __restrict__ hopwise,
                                               const float* __restrict__ headwise){
  __shared__ float  sgam[8];
  __shared__ float  shop0;
  __shared__ float2 part[4*32*9];   // [slot][lane][m0(4)+m1(4)+ka]
  int tid = threadIdx.x;
  if(tid < 8){
    float mx = -1e30f;
    for(int hh=0; hh<8; hh++) mx = fmaxf(mx, headwise[hh*2]);
    float ss = 0.f;
    for(int hh=0; hh<8; hh++) ss += expf(headwise[hh*2]-mx);
    sgam[tid] = hopwise[1] * expf(headwise[tid*2]-mx) / ss;
  }
  if(tid == 8) shop0 = hopwise[0];
  if(blockIdx.x == 0 && tid == 9) g_work = 0;   // reset tile queue for next graph replay
  __syncthreads();

  int w    = tid >> 5;
  int slot = w >> 1;                 // 0..3
  int sub  = w & 1;
  int n    = blockIdx.x*4 + slot;    // grid = NN/4 blocks
  int lane = tid & 31;
  int h8   = (lane >> 2) << 3;
  int beg = colp(n), end = colp(n+1);
  int half = (end - beg + 1) >> 1;
  int mbg = beg + sub*half;
  int mnd = sub ? end : (beg + half);

  U2 m0p[4], m1p[4];
  #pragma unroll
  for(int j=0;j<4;j++){ m0p[j].f = make_float2(0.f,0.f); m1p[j].f = make_float2(0.f,0.f); }
  float ka0 = 0.f, ka1 = 0.f;

  int e = mbg;
  for(; e+1 < mnd; e += 2){
    int rA = g_srow[e];   float nA = g_snorm[e];
    int rB = g_srow[e+1]; float nB = g_snorm[e+1];
    __half2 khA = *(const __half2*)&g_Kh[rA*64 + 2*lane];
    uint4   vvA = *(const uint4*)  &g_Vh[rA*64 + h8];
    __half2 khB = *(const __half2*)&g_Kh[rB*64 + 2*lane];
    uint4   vvB = *(const uint4*)  &g_Vh[rB*64 + h8];
    p1edge(nA, khA, vvA, ka0, ka1, m0p, m1p);
    p1edge(nB, khB, vvB, ka0, ka1, m0p, m1p);
  }
  if(e < mnd){
    int rA = g_srow[e]; float nA = g_snorm[e];
    __half2 khA = *(const __half2*)&g_Kh[rA*64 + 2*lane];
    uint4   vvA = *(const uint4*)  &g_Vh[rA*64 + h8];
    p1edge(nA, khA, vvA, ka0, ka1, m0p, m1p);
  }

  // combine the two warps' partials
  float2* pp = &part[(slot*32 + lane)*9];
  if(sub){
    pp[0]=m0p[0].f; pp[1]=m0p[1].f; pp[2]=m0p[2].f; pp[3]=m0p[3].f;
    pp[4]=m1p[0].f; pp[5]=m1p[1].f; pp[6]=m1p[2].f; pp[7]=m1p[3].f;
    pp[8]=make_float2(ka0, ka1);
  }
  __syncthreads();
  if(sub) return;
  #pragma unroll
  for(int j=0;j<4;j++){
    float2 q0 = pp[j], q1 = pp[4+j];
    m0p[j].f.x += q0.x; m0p[j].f.y += q0.y;
    m1p[j].f.x += q1.x; m1p[j].f.y += q1.y;
  }
  { float2 kk = pp[8]; ka0 += kk.x; ka1 += kk.y; }

  float m0[8], m1[8];
  #pragma unroll
  for(int j=0;j<4;j++){
    m0[2*j] = m0p[j].f.x; m0[2*j+1] = m0p[j].f.y;
    m1[2*j] = m1p[j].f.x; m1[2*j+1] = m1p[j].f.y;
  }
  {
    union { uint4 u; __half2 h[4]; } p;
    p.h[0]=__floats2half2_rn(m0[0],m0[1]); p.h[1]=__floats2half2_rn(m0[2],m0[3]);
    p.h[2]=__floats2half2_rn(m0[4],m0[5]); p.h[3]=__floats2half2_rn(m0[6],m0[7]);
    *(uint4*)&g_M1h[(size_t)n*512 + lane*8] = p.u;
    p.h[0]=__floats2half2_rn(m1[0],m1[1]); p.h[1]=__floats2half2_rn(m1[2],m1[3]);
    p.h[2]=__floats2half2_rn(m1[4],m1[5]); p.h[3]=__floats2half2_rn(m1[6],m1[7]);
    *(uint4*)&g_M1h[(size_t)n*512 + 256 + lane*8] = p.u;
  }
  *(__half2*)&g_K1h[n*64 + 2*lane] = __floats2half2_rn(ka0, ka1);

  float2 qv = *(const float2*)&g_Q[n*64 + 2*lane];
  float p[8];
  #pragma unroll
  for(int j=0;j<8;j++) p[j] = qv.x*m0[j] + qv.y*m1[j];
  #pragma unroll
  for(int j=0;j<8;j++){
    p[j] += __shfl_xor_sync(FULLMASK, p[j], 1);
    p[j] += __shfl_xor_sync(FULLMASK, p[j], 2);
  }
  float c = qv.x*ka0 + qv.y*ka1;
  c += __shfl_xor_sync(FULLMASK, c, 1);
  c += __shfl_xor_sync(FULLMASK, c, 2);
  int h = lane >> 2, sb = lane & 3;
  if(sb < 2){
    bool lo = (sb == 0);
    float r0 = lo ? p[0] : p[4];
    float r1 = lo ? p[1] : p[5];
    float r2 = lo ? p[2] : p[6];
    float r3 = lo ? p[3] : p[7];
    float inv = sgam[h] / (c + CSTF);
    float hp0 = shop0;
    const float4 vv = *(const float4*)&g_V[n*64 + h*8 + sb*4];
    float4 hv;
    hv.x = fmaf(vv.x, hp0, inv*r0);
    hv.y = fmaf(vv.y, hp0, inv*r1);
    hv.z = fmaf(vv.z, hp0, inv*r2);
    hv.w = fmaf(vv.w, hp0, inv*r3);
    *(float4*)&g_hidden[n*64 + h*8 + sb*4] = hv;
  }
  if(lane == 0) g_cur[n] = 0;
}

// ---------------- pass3 edge body ----------------
__device__ __forceinline__ void p3edge(float nrm, uint4 a, uint4 b, __half2 kv,
                                       U2* ma, U2* mb, U2& kap){
  unsigned long long N2; PACK2(N2, nrm);
  U2 t;
  t.f = __half22float2(*(__half2*)&a.x); FMA2(ma[0].u, N2, t.u);
  t.f = __half22float2(*(__half2*)&a.y); FMA2(ma[1].u, N2, t.u);
  t.f = __half22float2(*(__half2*)&a.z); FMA2(ma[2].u, N2, t.u);
  t.f = __half22float2(*(__half2*)&a.w); FMA2(ma[3].u, N2, t.u);
  t.f = __half22float2(*(__half2*)&b.x); FMA2(mb[0].u, N2, t.u);
  t.f = __half22float2(*(__half2*)&b.y); FMA2(mb[1].u, N2, t.u);
  t.f = __half22float2(*(__half2*)&b.z); FMA2(mb[2].u, N2, t.u);
  t.f = __half22float2(*(__half2*)&b.w); FMA2(mb[3].u, N2, t.u);
  t.f = __half22float2(kv);              FMA2(kap.u,  N2, t.u);
}

// ---------------- hop 2 + fused output GEMM (all 8 warps) ----------------
__global__ void __launch_bounds__(256) k_pass3(const float* __restrict__ hopwise,
                                               const float* __restrict__ headwise,
                                               const float* __restrict__ Wo,
                                               const float* __restrict__ bo,
                                               float* __restrict__ dout){
  __shared__ float  sgam[8];
  __shared__ float  hs[64*10];
  __shared__ float2 wos[2048];
  __shared__ float2 bos[32];
  int tid = threadIdx.x;
  if(tid < 8){
    float mx = -1e30f;
    for(int hh=0; hh<8; hh++) mx = fmaxf(mx, headwise[hh*2+1]);
    float ss = 0.f;
    for(int hh=0; hh<8; hh++) ss += expf(headwise[hh*2+1]-mx);
    sgam[tid] = hopwise[2] * expf(headwise[tid*2+1]-mx) / ss;
  }
  for(int idx = tid; idx < 4096; idx += 256){
    int wi = idx >> 6, wo = idx & 63;
    ((float*)&wos[wi*32 + (wo & 31)])[wo >> 5] = Wo[idx];
  }
  if(tid < 32) bos[tid] = make_float2(bo[tid], bo[tid+32]);
  __syncthreads();

  int n    = (blockIdx.x*256 + tid) >> 5;
  int nw   = tid >> 5;
  int lane = tid & 31;
  int beg = colp(n), end = colp(n+1);
  U2 ma[4], mb[4], kap;
  #pragma unroll
  for(int j=0;j<4;j++){ ma[j].f = make_float2(0.f,0.f); mb[j].f = make_float2(0.f,0.f); }
  kap.f = make_float2(0.f,0.f);

  int e = beg;
  for(; e+1 < end; e += 2){
    int rA = g_srow[e];   float nA = g_snorm[e];
    int rB = g_srow[e+1]; float nB = g_snorm[e+1];
    const __half* MA = &g_M1h[(size_t)rA*512];
    const __half* MB = &g_M1h[(size_t)rB*512];
    uint4 aA = *(const uint4*)(MA + lane*8);
    uint4 bA = *(const uint4*)(MA + 256 + lane*8);
    __half2 kA = *(const __half2*)&g_K1h[rA*64 + 2*lane];
    uint4 aB = *(const uint4*)(MB + lane*8);
    uint4 bB = *(const uint4*)(MB + 256 + lane*8);
    __half2 kB = *(const __half2*)&g_K1h[rB*64 + 2*lane];
    p3edge(nA, aA, bA, kA, ma, mb, kap);
    p3edge(nB, aB, bB, kB, ma, mb, kap);
  }
  if(e < end){
    int rA = g_srow[e]; float nA = g_snorm[e];
    const __half* MA = &g_M1h[(size_t)rA*512];
    uint4 aA = *(const uint4*)(MA + lane*8);
    uint4 bA = *(const uint4*)(MA + 256 + lane*8);
    __half2 kA = *(const __half2*)&g_K1h[rA*64 + 2*lane];
    p3edge(nA, aA, bA, kA, ma, mb, kap);
  }

  float2 qv = *(const float2*)&g_Q[n*64 + 2*lane];
  float p[8];
  #pragma unroll
  for(int j=0;j<4;j++){
    p[2*j]   = qv.x*ma[j].f.x + qv.y*mb[j].f.x;
    p[2*j+1] = qv.x*ma[j].f.y + qv.y*mb[j].f.y;
  }
  #pragma unroll
  for(int j=0;j<8;j++){
    p[j] += __shfl_xor_sync(FULLMASK, p[j], 1);
    p[j] += __shfl_xor_sync(FULLMASK, p[j], 2);
  }
  float c = qv.x*kap.f.x + qv.y*kap.f.y;
  c += __shfl_xor_sync(FULLMASK, c, 1);
  c += __shfl_xor_sync(FULLMASK, c, 2);
  int h = lane >> 2, sub = lane & 3;
  if(sub < 2){
    bool lo = (sub == 0);
    float r0 = lo ? p[0] : p[4];
    float r1 = lo ? p[1] : p[5];
    float r2 = lo ? p[2] : p[6];
    float r3 = lo ? p[3] : p[7];
    float inv = sgam[h] / (c + CSTF);
    const float4 hv = *(const float4*)&g_hidden[n*64 + h*8 + sub*4];
    int ib = h*8 + sub*4;
    hs[(ib+0)*10 + nw] = hv.x + inv*r0;
    hs[(ib+1)*10 + nw] = hv.y + inv*r1;
    hs[(ib+2)*10 + nw] = hv.z + inv*r2;
    hs[(ib+3)*10 + nw] = hv.w + inv*r3;
  }
  __syncthreads();

  // ---- fused output GEMM: ALL 8 warps, 1 node/warp, 1 U2 acc/lane ----
  {
    U2 acc; acc.f = bos[lane];
    const unsigned long long* wsu = (const unsigned long long*)wos;
    #pragma unroll 4
    for(int i=0; i<64; i++){
      unsigned long long w = wsu[i*32 + lane];
      float xv = hs[i*10 + nw];
      unsigned long long xx; PACK2(xx, xv);
      FMA2(acc.u, xx, w);
    }
    dout[n*64 + lane]      = acc.f.x;
    dout[n*64 + lane + 32] = acc.f.y;
  }
}

// ---------------- launch ----------------
extern "C" void kernel_launch(void* const* d_in, const int* in_sizes, int n_in,
                              void* d_out, int out_size){
  const float* x        = (const float*)d_in[0];
  const int*   ei       = (const int*)  d_in[1];
  const float* Wq       = (const float*)d_in[3];
  const float* bq       = (const float*)d_in[4];
  const float* Wk       = (const float*)d_in[5];
  const float* bk       = (const float*)d_in[6];
  const float* Wv       = (const float*)d_in[7];
  const float* bv       = (const float*)d_in[8];
  const float* Wo       = (const float*)d_in[9];
  const float* bo       = (const float*)d_in[10];
  const float* hopwise  = (const float*)d_in[11];
  const float* headwise = (const float*)d_in[12];
  float* out = (float*)d_out;

  cudaFuncSetAttribute(k_fused, cudaFuncAttributeMaxDynamicSharedMemorySize, SMEMF);

  k_fused <<<GRIDF, 256, SMEMF>>>(ei, x, Wq, bq, Wk, bk, Wv, bv);
  k_pass1 <<<NN/4, 256>>>(hopwise, headwise);
  k_pass3 <<<NN/8, 256>>>(hopwise, headwise, Wo, bo, out);
}

// round 17
// speedup vs baseline: 1.0576x; 1.0576x over previous
#include <cuda_runtime.h>
#include <cuda_fp16.h>

#define NN 20000
#define NE 320000
#define NB 25
#define SEG 800
#define FULLMASK 0xffffffffu
#define CSTF 1e-5f
#define CSRB 148
#define NTILES 313          // 313*64 = 20032 >= 20000

#define FMA2(acc, a, b) asm("fma.rn.f32x2 %0, %1, %2, %0;" : "+l"(acc) : "l"(a), "l"(b))
#define PACK2(xx, xv)   asm("mov.b64 %0, {%1, %1};" : "=l"(xx) : "f"(xv))

union U2 { unsigned long long u; float2 f; };

// 1 + elu applied lazily to raw Q
__device__ __forceinline__ float2 act2(float2 q){
  q.x = (q.x > 0.f) ? (q.x + 1.f) : __expf(q.x);
  q.y = (q.y > 0.f) ? (q.y + 1.f) : __expf(q.y);
  return q;
}

// ---------------- device scratch (static; every call restores zeros) ----------------
__device__ float  g_Q[NN*64];          // RAW x@Wq+bq (activation applied at use)
__device__ __half g_Kh[NN*64];
__device__ __half g_Vh[NN*64];
__device__ float  g_V[NN*64];
__device__ float  g_hidden[NN*64];
__device__ __half g_M1h[(size_t)NN*512];
__device__ __half g_K1h[NN*64];
__device__ float  g_deginv[NN];
__device__ int    g_cnt[NN];
__device__ int    g_cur[NN];
__device__ int    g_colptr[NN+1];
__device__ int    g_bsum[NB];
__device__ int    g_boff[NB+1];
__device__ int    g_srow[NE];
__device__ float  g_snorm[NE];
__device__ volatile int g_ph1, g_ph2, g_ph3;

__device__ __forceinline__ void detect64(const int* __restrict__ ei, int tid, int* s64){
  if(tid < 32){
    bool z = (ei[2*(tid*9973)+1] == 0);
    unsigned bal = __ballot_sync(FULLMASK, z);
    if(tid==0) *s64 = (bal == FULLMASK) ? 1 : 0;
  }
}

__device__ __forceinline__ int colp(int i){
  return g_colptr[i] + g_boff[i/SEG];
}

// ============ fused launch: 148 CSR blocks + 939 GEMM blocks (1 per tile x matrix) ======
#define SMEMF (16896 + 16384 + 256)
__global__ void __launch_bounds__(256,5) k_fused(const int* __restrict__ ei,
    const float* __restrict__ x,
    const float* __restrict__ Wq, const float* __restrict__ bq,
    const float* __restrict__ Wk, const float* __restrict__ bk,
    const float* __restrict__ Wv, const float* __restrict__ bv){
  extern __shared__ __align__(16) char dsm[];
  int tid = threadIdx.x;
  int bid = blockIdx.x;

  if(bid < CSRB){
    // -------- CSR builder --------
    int* s     = (int*)dsm;
    int* wtot  = (int*)(dsm + SEG*4);
    int* ps64  = (int*)(dsm + SEG*4 + 32);
    int* sboff = (int*)(dsm + SEG*4 + 64);
    detect64(ei, tid, ps64);
    __syncthreads();
    int s64 = *ps64;

    // phase 1: degree histogram
    for(int e = bid*256 + tid; e < NE; e += CSRB*256){
      int c = s64 ? ei[2*(NE+e)] : ei[NE+e];
      atomicAdd(&g_cnt[c], 1);
    }
    __threadfence();
    __syncthreads();
    if(tid == 0){
      atomicAdd((int*)&g_ph1, 1);
      while(g_ph1 < CSRB) {}
    }
    __syncthreads();
    __threadfence();

    // phase 2: per-segment scan + deginv; zero g_cnt
    if(bid < NB){
      for(int i=tid; i<SEG; i+=256){ s[i] = __ldcg(&g_cnt[bid*SEG+i]); g_cnt[bid*SEG+i] = 0; }
      __syncthreads();
      int c0=0,c1=0,c2=0,c3=0,v=0;
      if(tid < 200){
        c0=s[4*tid]; c1=s[4*tid+1]; c2=s[4*tid+2]; c3=s[4*tid+3];
        v = c0+c1+c2+c3;
      }
      int lane = tid & 31, wid = tid >> 5;
      int xx = v;
      #pragma unroll
      for(int off=1; off<32; off<<=1){ int y=__shfl_up_sync(FULLMASK,xx,off); if(lane>=off) xx+=y; }
      if(lane==31) wtot[wid] = xx;
      __syncthreads();
      if(tid < 32){
        int w = (tid < 7) ? wtot[tid] : 0;
        #pragma unroll
        for(int off=1; off<32; off<<=1){ int y=__shfl_up_sync(FULLMASK,w,off); if(tid>=off) w+=y; }
        if(tid < 7) wtot[tid] = w;
        if(tid == 6) g_bsum[bid] = w;
      }
      __syncthreads();
      if(tid < 200){
        int pre = xx - v + (wid>0 ? wtot[wid-1] : 0);
        int base = bid*SEG + 4*tid;
        g_colptr[base+0] = pre;
        g_colptr[base+1] = pre + c0;
        g_colptr[base+2] = pre + c0 + c1;
        g_colptr[base+3] = pre + c0 + c1 + c2;
        g_deginv[base+0] = c0 ? rsqrtf((float)c0) : 0.f;
        g_deginv[base+1] = c1 ? rsqrtf((float)c1) : 0.f;
        g_deginv[base+2] = c2 ? rsqrtf((float)c2) : 0.f;
        g_deginv[base+3] = c3 ? rsqrtf((float)c3) : 0.f;
      }
    }
    __threadfence();
    __syncthreads();
    if(tid == 0){
      atomicAdd((int*)&g_ph2, 1);
      while(g_ph2 < CSRB) {}
      if(bid == 0) g_ph1 = 0;
    }
    __syncthreads();
    __threadfence();

    // phase 3: block offsets + scatter
    if(tid < 32){
      int v = (tid < NB) ? __ldcg(&g_bsum[tid]) : 0;
      int xx = v;
      #pragma unroll
      for(int off=1; off<32; off<<=1){ int y=__shfl_up_sync(FULLMASK,xx,off); if(tid>=off) xx+=y; }
      if(tid < NB) sboff[tid] = xx - v;
      if(bid == 0){
        if(tid < NB) g_boff[tid] = xx - v;
        if(tid == 31) g_boff[NB] = NE;
      }
    }
    __syncthreads();
    for(int e = bid*256 + tid; e < NE; e += CSRB*256){
      int r = s64 ? ei[2*e]      : ei[e];
      int c = s64 ? ei[2*(NE+e)] : ei[NE+e];
      int pos = __ldcg(&g_colptr[c]) + sboff[c/SEG] + atomicAdd(&g_cur[c], 1);
      g_srow[pos]  = r;
      g_snorm[pos] = __ldcg(&g_deginv[r]) * __ldcg(&g_deginv[c]);
    }
    __threadfence();
    __syncthreads();
    if(tid == 0){
      atomicAdd((int*)&g_ph3, 1);
      if(bid == 0){
        while(g_ph3 < CSRB) {}
        g_ph2 = 0; g_ph3 = 0;
      }
    }
    return;
  }

  // -------- QKV GEMM: one (tile, matrix) per block --------
  int gb   = bid - CSRB;                   // 0..938
  int mat  = gb / NTILES;                  // 0=Q 1=K 2=V
  int tile = gb - mat*NTILES;              // 0..312
  int nb   = tile*64;
  const float* W = (mat==0) ? Wq : (mat==1) ? Wk : Wv;
  const float* b = (mat==0) ? bq : (mat==1) ? bk : bv;

  float*  xst = (float*)dsm;                        // [i*66 + n]
  float2* ws2 = (float2*)(dsm + 16896);             // [i*32 + op]
  float2* bs2 = (float2*)(dsm + 16896 + 16384);
  for(int idx = tid; idx < 4096; idx += 256){
    int n = idx >> 6, i = idx & 63;
    xst[i*66 + n] = (nb+n < NN) ? x[(nb+n)*64 + i] : 0.f;
    int wi = idx >> 6, wo = idx & 63;
    ((float*)&ws2[wi*32 + (wo & 31)])[wo >> 5] = W[idx];
  }
  if(tid < 32) bs2[tid] = make_float2(b[tid], b[tid+32]);
  __syncthreads();

  int op = tid & 31;
  int ng = (tid >> 5) << 3;
  U2 a0[4], a1[4];
  { float2 bb = bs2[op];
    unsigned long long p0, p1; PACK2(p0, bb.x); PACK2(p1, bb.y);
    #pragma unroll
    for(int g=0;g<4;g++){ a0[g].u = p0; a1[g].u = p1; } }

  const unsigned long long* wsu = (const unsigned long long*)ws2;
  #pragma unroll 4
  for(int i=0; i<64; i++){
    U2 w; w.u = wsu[i*32 + op];
    unsigned long long w0, w1; PACK2(w0, w.f.x); PACK2(w1, w.f.y);
    const unsigned long long* xp = (const unsigned long long*)&xst[i*66 + ng];
    #pragma unroll
    for(int g=0;g<4;g++){
      unsigned long long xx = xp[g];
      FMA2(a0[g].u, xx, w0);
      FMA2(a1[g].u, xx, w1);
    }
  }

  #pragma unroll
  for(int g=0;g<4;g++){
    int n0 = nb + ng + 2*g;
    #pragma unroll
    for(int u=0;u<2;u++){
      int n = n0 + u;
      if(n < NN){
        float va = u ? a0[g].f.y : a0[g].f.x;
        float vb = u ? a1[g].f.y : a1[g].f.x;
        if(mat == 0){
          // RAW Q — activation applied at use in pass1/pass3
          g_Q[n*64+op] = va; g_Q[n*64+op+32] = vb;
        } else if(mat == 1){
          va = (va > 0.f) ? (va + 1.f) : __expf(va);
          vb = (vb > 0.f) ? (vb + 1.f) : __expf(vb);
          g_Kh[n*64+op] = __float2half_rn(va); g_Kh[n*64+op+32] = __float2half_rn(vb);
        } else {
          g_V[n*64+op] = va; g_V[n*64+op+32] = vb;
          g_Vh[n*64+op] = __float2half_rn(va); g_Vh[n*64+op+32] = __float2half_rn(vb);
        }
      }
    }
  }
}

// ---------------- pass1 edge body ----------------
__device__ __forceinline__ void p1edge(float nrm, __half2 kh, uint4 vv,
                                       float& ka0, float& ka1, U2* m0p, U2* m1p){
  float2 kf = __half22float2(kh);
  float a0 = nrm*kf.x, a1 = nrm*kf.y;
  ka0 += a0; ka1 += a1;
  unsigned long long A0, A1; PACK2(A0, a0); PACK2(A1, a1);
  U2 v01, v23, v45, v67;
  v01.f = __half22float2(*(__half2*)&vv.x);
  v23.f = __half22float2(*(__half2*)&vv.y);
  v45.f = __half22float2(*(__half2*)&vv.z);
  v67.f = __half22float2(*(__half2*)&vv.w);
  FMA2(m0p[0].u, A0, v01.u); FMA2(m0p[1].u, A0, v23.u);
  FMA2(m0p[2].u, A0, v45.u); FMA2(m0p[3].u, A0, v67.u);
  FMA2(m1p[0].u, A1, v01.u); FMA2(m1p[1].u, A1, v23.u);
  FMA2(m1p[2].u, A1, v45.u); FMA2(m1p[3].u, A1, v67.u);
}

// ---------------- hop 1: unroll-2 edge loop ----------------
__global__ void __launch_bounds__(256) k_pass1(const float* __restrict__ hopwise,
                                               const float* __restrict__ headwise){
  __shared__ float sgam[8];
  __shared__ float shop0;
  int tid = threadIdx.x;
  if(tid < 8){
    float mx = -1e30f;
    for(int hh=0; hh<8; hh++) mx = fmaxf(mx, headwise[hh*2]);
    float ss = 0.f;
    for(int hh=0; hh<8; hh++) ss += expf(headwise[hh*2]-mx);
    sgam[tid] = hopwise[1] * expf(headwise[tid*2]-mx) / ss;
  }
  if(tid == 8) shop0 = hopwise[0];
  __syncthreads();

  int n    = (blockIdx.x*256 + tid) >> 5;
  int lane = tid & 31;
  int h8   = (lane >> 2) << 3;
  int beg = colp(n), end = colp(n+1);
  U2 m0p[4], m1p[4];
  #pragma unroll
  for(int j=0;j<4;j++){ m0p[j].f = make_float2(0.f,0.f); m1p[j].f = make_float2(0.f,0.f); }
  float ka0 = 0.f, ka1 = 0.f;

  int e = beg;
  for(; e+1 < end; e += 2){
    int rA = g_srow[e];   float nA = g_snorm[e];
    int rB = g_srow[e+1]; float nB = g_snorm[e+1];
    __half2 khA = *(const __half2*)&g_Kh[rA*64 + 2*lane];
    uint4   vvA = *(const uint4*)  &g_Vh[rA*64 + h8];
    __half2 khB = *(const __half2*)&g_Kh[rB*64 + 2*lane];
    uint4   vvB = *(const uint4*)  &g_Vh[rB*64 + h8];
    p1edge(nA, khA, vvA, ka0, ka1, m0p, m1p);
    p1edge(nB, khB, vvB, ka0, ka1, m0p, m1p);
  }
  if(e < end){
    int rA = g_srow[e]; float nA = g_snorm[e];
    __half2 khA = *(const __half2*)&g_Kh[rA*64 + 2*lane];
    uint4   vvA = *(const uint4*)  &g_Vh[rA*64 + h8];
    p1edge(nA, khA, vvA, ka0, ka1, m0p, m1p);
  }

  float m0[8], m1[8];
  #pragma unroll
  for(int j=0;j<4;j++){
    m0[2*j] = m0p[j].f.x; m0[2*j+1] = m0p[j].f.y;
    m1[2*j] = m1p[j].f.x; m1[2*j+1] = m1p[j].f.y;
  }
  {
    union { uint4 u; __half2 h[4]; } p;
    p.h[0]=__floats2half2_rn(m0[0],m0[1]); p.h[1]=__floats2half2_rn(m0[2],m0[3]);
    p.h[2]=__floats2half2_rn(m0[4],m0[5]); p.h[3]=__floats2half2_rn(m0[6],m0[7]);
    *(uint4*)&g_M1h[(size_t)n*512 + lane*8] = p.u;
    p.h[0]=__floats2half2_rn(m1[0],m1[1]); p.h[1]=__floats2half2_rn(m1[2],m1[3]);
    p.h[2]=__floats2half2_rn(m1[4],m1[5]); p.h[3]=__floats2half2_rn(m1[6],m1[7]);
    *(uint4*)&g_M1h[(size_t)n*512 + 256 + lane*8] = p.u;
  }
  *(__half2*)&g_K1h[n*64 + 2*lane] = __floats2half2_rn(ka0, ka1);

  float2 qv = act2(*(const float2*)&g_Q[n*64 + 2*lane]);   // lazy 1+elu
  float p[8];
  #pragma unroll
  for(int j=0;j<8;j++) p[j] = qv.x*m0[j] + qv.y*m1[j];
  #pragma unroll
  for(int j=0;j<8;j++){
    p[j] += __shfl_xor_sync(FULLMASK, p[j], 1);
    p[j] += __shfl_xor_sync(FULLMASK, p[j], 2);
  }
  float c = qv.x*ka0 + qv.y*ka1;
  c += __shfl_xor_sync(FULLMASK, c, 1);
  c += __shfl_xor_sync(FULLMASK, c, 2);
  int h = lane >> 2, sub = lane & 3;
  if(sub < 2){
    bool lo = (sub == 0);
    float r0 = lo ? p[0] : p[4];
    float r1 = lo ? p[1] : p[5];
    float r2 = lo ? p[2] : p[6];
    float r3 = lo ? p[3] : p[7];
    float inv = sgam[h] / (c + CSTF);
    float hp0 = shop0;
    const float4 vv = *(const float4*)&g_V[n*64 + h*8 + sub*4];
    float4 hv;
    hv.x = fmaf(vv.x, hp0, inv*r0);
    hv.y = fmaf(vv.y, hp0, inv*r1);
    hv.z = fmaf(vv.z, hp0, inv*r2);
    hv.w = fmaf(vv.w, hp0, inv*r3);
    *(float4*)&g_hidden[n*64 + h*8 + sub*4] = hv;
  }
  if(lane == 0) g_cur[n] = 0;
}

// ---------------- pass3 edge body ----------------
__device__ __forceinline__ void p3edge(float nrm, uint4 a, uint4 b, __half2 kv,
                                       U2* ma, U2* mb, U2& kap){
  unsigned long long N2; PACK2(N2, nrm);
  U2 t;
  t.f = __half22float2(*(__half2*)&a.x); FMA2(ma[0].u, N2, t.u);
  t.f = __half22float2(*(__half2*)&a.y); FMA2(ma[1].u, N2, t.u);
  t.f = __half22float2(*(__half2*)&a.z); FMA2(ma[2].u, N2, t.u);
  t.f = __half22float2(*(__half2*)&a.w); FMA2(ma[3].u, N2, t.u);
  t.f = __half22float2(*(__half2*)&b.x); FMA2(mb[0].u, N2, t.u);
  t.f = __half22float2(*(__half2*)&b.y); FMA2(mb[1].u, N2, t.u);
  t.f = __half22float2(*(__half2*)&b.z); FMA2(mb[2].u, N2, t.u);
  t.f = __half22float2(*(__half2*)&b.w); FMA2(mb[3].u, N2, t.u);
  t.f = __half22float2(kv);              FMA2(kap.u,  N2, t.u);
}

// ---------------- hop 2 + fused output GEMM (all 8 warps) ----------------
__global__ void __launch_bounds__(256) k_pass3(const float* __restrict__ hopwise,
                                               const float* __restrict__ headwise,
                                               const float* __restrict__ Wo,
                                               const float* __restrict__ bo,
                                               float* __restrict__ dout){
  __shared__ float  sgam[8];
  __shared__ float  hs[64*10];
  __shared__ float2 wos[2048];
  __shared__ float2 bos[32];
  int tid = threadIdx.x;
  if(tid < 8){
    float mx = -1e30f;
    for(int hh=0; hh<8; hh++) mx = fmaxf(mx, headwise[hh*2+1]);
    float ss = 0.f;
    for(int hh=0; hh<8; hh++) ss += expf(headwise[hh*2+1]-mx);
    sgam[tid] = hopwise[2] * expf(headwise[tid*2+1]-mx) / ss;
  }
  for(int idx = tid; idx < 4096; idx += 256){
    int wi = idx >> 6, wo = idx & 63;
    ((float*)&wos[wi*32 + (wo & 31)])[wo >> 5] = Wo[idx];
  }
  if(tid < 32) bos[tid] = make_float2(bo[tid], bo[tid+32]);
  __syncthreads();

  int n    = (blockIdx.x*256 + tid) >> 5;
  int nw   = tid >> 5;
  int lane = tid & 31;
  int beg = colp(n), end = colp(n+1);
  U2 ma[4], mb[4], kap;
  #pragma unroll
  for(int j=0;j<4;j++){ ma[j].f = make_float2(0.f,0.f); mb[j].f = make_float2(0.f,0.f); }
  kap.f = make_float2(0.f,0.f);

  int e = beg;
  for(; e+1 < end; e += 2){
    int rA = g_srow[e];   float nA = g_snorm[e];
    int rB = g_srow[e+1]; float nB = g_snorm[e+1];
    const __half* MA = &g_M1h[(size_t)rA*512];
    const __half* MB = &g_M1h[(size_t)rB*512];
    uint4 aA = *(const uint4*)(MA + lane*8);
    uint4 bA = *(const uint4*)(MA + 256 + lane*8);
    __half2 kA = *(const __half2*)&g_K1h[rA*64 + 2*lane];
    uint4 aB = *(const uint4*)(MB + lane*8);
    uint4 bB = *(const uint4*)(MB + 256 + lane*8);
    __half2 kB = *(const __half2*)&g_K1h[rB*64 + 2*lane];
    p3edge(nA, aA, bA, kA, ma, mb, kap);
    p3edge(nB, aB, bB, kB, ma, mb, kap);
  }
  if(e < end){
    int rA = g_srow[e]; float nA = g_snorm[e];
    const __half* MA = &g_M1h[(size_t)rA*512];
    uint4 aA = *(const uint4*)(MA + lane*8);
    uint4 bA = *(const uint4*)(MA + 256 + lane*8);
    __half2 kA = *(const __half2*)&g_K1h[rA*64 + 2*lane];
    p3edge(nA, aA, bA, kA, ma, mb, kap);
  }

  float2 qv = act2(*(const float2*)&g_Q[n*64 + 2*lane]);   // lazy 1+elu
  float p[8];
  #pragma unroll
  for(int j=0;j<4;j++){
    p[2*j]   = qv.x*ma[j].f.x + qv.y*mb[j].f.x;
    p[2*j+1] = qv.x*ma[j].f.y + qv.y*mb[j].f.y;
  }
  #pragma unroll
  for(int j=0;j<8;j++){
    p[j] += __shfl_xor_sync(FULLMASK, p[j], 1);
    p[j] += __shfl_xor_sync(FULLMASK, p[j], 2);
  }
  float c = qv.x*kap.f.x + qv.y*kap.f.y;
  c += __shfl_xor_sync(FULLMASK, c, 1);
  c += __shfl_xor_sync(FULLMASK, c, 2);
  int h = lane >> 2, sub = lane & 3;
  if(sub < 2){
    bool lo = (sub == 0);
    float r0 = lo ? p[0] : p[4];
    float r1 = lo ? p[1] : p[5];
    float r2 = lo ? p[2] : p[6];
    float r3 = lo ? p[3] : p[7];
    float inv = sgam[h] / (c + CSTF);
    const float4 hv = *(const float4*)&g_hidden[n*64 + h*8 + sub*4];
    int ib = h*8 + sub*4;
    hs[(ib+0)*10 + nw] = hv.x + inv*r0;
    hs[(ib+1)*10 + nw] = hv.y + inv*r1;
    hs[(ib+2)*10 + nw] = hv.z + inv*r2;
    hs[(ib+3)*10 + nw] = hv.w + inv*r3;
  }
  __syncthreads();

  // ---- fused output GEMM: ALL 8 warps, 1 node/warp, 1 U2 acc/lane ----
  {
    U2 acc; acc.f = bos[lane];
    const unsigned long long* wsu = (const unsigned long long*)wos;
    #pragma unroll 4
    for(int i=0; i<64; i++){
      unsigned long long w = wsu[i*32 + lane];
      float xv = hs[i*10 + nw];
      unsigned long long xx; PACK2(xx, xv);
      FMA2(acc.u, xx, w);
    }
    dout[n*64 + lane]      = acc.f.x;
    dout[n*64 + lane + 32] = acc.f.y;
  }
}

// ---------------- launch ----------------
extern "C" void kernel_launch(void* const* d_in, const int* in_sizes, int n_in,
                              void* d_out, int out_size){
  const float* x        = (const float*)d_in[0];
  const int*   ei       = (const int*)  d_in[1];
  const float* Wq       = (const float*)d_in[3];
  const float* bq       = (const float*)d_in[4];
  const float* Wk       = (const float*)d_in[5];
  const float* bk       = (const float*)d_in[6];
  const float* Wv       = (const float*)d_in[7];
  const float* bv       = (const float*)d_in[8];
  const float* Wo       = (const float*)d_in[9];
  const float* bo       = (const float*)d_in[10];
  const float* hopwise  = (const float*)d_in[11];
  const float* headwise = (const float*)d_in[12];
  float* out = (float*)d_out;

  cudaFuncSetAttribute(k_fused, cudaFuncAttributeMaxDynamicSharedMemorySize, SMEMF);

  k_fused <<<CSRB + 3*NTILES, 256, SMEMF>>>(ei, x, Wq, bq, Wk, bk, Wv, bv);
  k_pass1 <<<NN/8, 256>>>(hopwise, headwise);
  k_pass3 <<<NN/8, 256>>>(hopwise, headwise, Wo, bo, out);
}